// round 14
// baseline (speedup 1.0000x reference)
#include <cuda_runtime.h>
#include <cuda_bf16.h>
#include <cstdint>

// Problem dims (fixed per reference)
#define NROWS 8192
#define NFEAT 512
#define NHID  256
#define HDIM  768   // NHID + NFEAT

// -------------------- scratch (device globals; no allocations allowed) ----
// t1[8192*256] h1[8192*256] t2[8192*256] cat[8192*768] o4[8192*768]
// o5[8192*768] o6[8192*512]
__device__ float g_scratch[3 * NROWS * NHID + 3 * NROWS * HDIM + NROWS * NFEAT];

// -------------------- helpers ---------------------------------------------
__device__ __forceinline__ void stchunk(void* dst, float4 x, float4 y) {
    __nv_bfloat162 p0(__float2bfloat16(x.x), __float2bfloat16(x.y));
    __nv_bfloat162 p1(__float2bfloat16(x.z), __float2bfloat16(x.w));
    __nv_bfloat162 p2(__float2bfloat16(y.x), __float2bfloat16(y.y));
    __nv_bfloat162 p3(__float2bfloat16(y.z), __float2bfloat16(y.w));
    uint4 u;
    u.x = *(uint32_t*)&p0;
    u.y = *(uint32_t*)&p1;
    u.z = *(uint32_t*)&p2;
    u.w = *(uint32_t*)&p3;
    *(uint4*)dst = u;
}

__device__ __forceinline__ void ldsm_x4(uint32_t addr, uint32_t& r0, uint32_t& r1,
                                        uint32_t& r2, uint32_t& r3) {
    asm volatile("ldmatrix.sync.aligned.m8n8.x4.shared.b16 {%0,%1,%2,%3}, [%4];"
                 : "=r"(r0), "=r"(r1), "=r"(r2), "=r"(r3) : "r"(addr));
}
__device__ __forceinline__ void ldsm_x4_t(uint32_t addr, uint32_t& r0, uint32_t& r1,
                                          uint32_t& r2, uint32_t& r3) {
    asm volatile("ldmatrix.sync.aligned.m8n8.x4.trans.shared.b16 {%0,%1,%2,%3}, [%4];"
                 : "=r"(r0), "=r"(r1), "=r"(r2), "=r"(r3) : "r"(addr));
}
__device__ __forceinline__ void mma16816(float* d, const uint32_t* a, const uint32_t* b) {
    asm volatile(
        "mma.sync.aligned.m16n8k16.row.col.f32.bf16.bf16.f32 "
        "{%0,%1,%2,%3},{%4,%5,%6,%7},{%8,%9},{%0,%1,%2,%3};"
        : "+f"(d[0]), "+f"(d[1]), "+f"(d[2]), "+f"(d[3])
        : "r"(a[0]), "r"(a[1]), "r"(a[2]), "r"(a[3]), "r"(b[0]), "r"(b[1]));
}

// -------------------- GEMM: C[M,N](f32) = act(A[M,K]f32 @ B[K,N]f32 + bias) ----
// Block tile 128x128x32, 256 threads (8 warps as 2x4, warp tile 64x32).
// A, B converted to bf16 on the SMEM fill; 2-stage reg-staged double buffer.
// Requires: M%128==0, N%128==0, K%32==0, lda==K, ldb==N.
template <bool BIAS, bool RELU>
__global__ void __launch_bounds__(256, 1)
gemm_kernel(const float* __restrict__ A, const float* __restrict__ B,
            const float* __restrict__ bias, float* __restrict__ C,
            int M, int N, int K, int ldc) {
    __shared__ __nv_bfloat16 sA[2][128 * 32];
    __shared__ __nv_bfloat16 sB[2][32 * 128];

    const int tid  = threadIdx.x;
    const int lane = tid & 31;
    const int wid  = tid >> 5;
    const int bm   = blockIdx.y * 128;
    const int bn   = blockIdx.x * 128;
    const int warp_m = (wid >> 2) * 64;   // 0 / 64
    const int warp_n = (wid & 3) * 32;    // 0..96

    // loader decomposition: A = 512 16B-chunks (128 rows x 4), B = 512 (32 x 16)
    const int ar = tid >> 2;   // 0..63   (second chunk: row ar+64, same c)
    const int ac = tid & 3;
    const int bk = tid >> 4;   // 0..15   (second chunk: row bk+16, same c)
    const int bc = tid & 15;

    const float* Ap0 = A + (size_t)(bm + ar) * K + ac * 8;
    const float* Ap1 = Ap0 + (size_t)64 * K;
    const float* Bp0 = B + (size_t)bk * N + bn + bc * 8;
    const float* Bp1 = Bp0 + (size_t)16 * N;

    // swizzled SMEM byte offsets (chunk = 16B = 8 bf16)
    // A row r (32 bf16 = 4 chunks): phys_chunk = c ^ ((r>>1)&3)  -> ldmatrix conflict-free
    // B row k (128 bf16 = 16 chunks): phys_chunk = c ^ (k&7)
    const uint32_t sa_off0 = 2u * (ar * 32 + ((ac ^ ((ar >> 1) & 3)) * 8));
    const uint32_t sa_off1 = sa_off0 + 2u * 64 * 32;          // (ar+64): same xor
    const uint32_t sb_off0 = 2u * (bk * 128 + ((bc ^ (bk & 7)) * 8));
    const uint32_t sb_off1 = sb_off0 + 2u * 16 * 128;          // (bk+16): same xor

    float4 ra[4], rb[4];
    float acc[4][4][4];
#pragma unroll
    for (int i = 0; i < 4; i++)
#pragma unroll
        for (int j = 0; j < 4; j++)
#pragma unroll
            for (int r = 0; r < 4; r++) acc[i][j][r] = 0.0f;

    const int ksteps = K >> 5;

    auto LOAD = [&](int kt) {
        const float* p = Ap0 + kt * 32;
        ra[0] = __ldg((const float4*)p);
        ra[1] = __ldg((const float4*)(p + 4));
        p = Ap1 + kt * 32;
        ra[2] = __ldg((const float4*)p);
        ra[3] = __ldg((const float4*)(p + 4));
        p = Bp0 + (size_t)kt * 32 * N;
        rb[0] = __ldg((const float4*)p);
        rb[1] = __ldg((const float4*)(p + 4));
        p = Bp1 + (size_t)kt * 32 * N;
        rb[2] = __ldg((const float4*)p);
        rb[3] = __ldg((const float4*)(p + 4));
    };
    auto STS = [&](int s) {
        char* a = (char*)&sA[s][0];
        char* b = (char*)&sB[s][0];
        stchunk(a + sa_off0, ra[0], ra[1]);
        stchunk(a + sa_off1, ra[2], ra[3]);
        stchunk(b + sb_off0, rb[0], rb[1]);
        stchunk(b + sb_off1, rb[2], rb[3]);
    };
    auto COMPUTE = [&](int s) {
        uint32_t abase = (uint32_t)__cvta_generic_to_shared(&sA[s][0]);
        uint32_t bbase = (uint32_t)__cvta_generic_to_shared(&sB[s][0]);
#pragma unroll
        for (int kk = 0; kk < 2; kk++) {   // two k16 steps per BK=32
            uint32_t af[4][4];
#pragma unroll
            for (int mt = 0; mt < 4; mt++) {
                int r = warp_m + mt * 16 + (lane & 7) + ((lane >> 3) & 1) * 8;
                int c = kk * 2 + (lane >> 4);
                uint32_t addr = abase + 2u * (r * 32 + ((c ^ ((r >> 1) & 3)) * 8));
                ldsm_x4(addr, af[mt][0], af[mt][1], af[mt][2], af[mt][3]);
            }
            uint32_t bf[4][2];
#pragma unroll
            for (int np = 0; np < 2; np++) {  // each x4.trans covers two n-tiles
                int kr = kk * 16 + (lane & 7) + ((lane >> 3) & 1) * 8;
                int c  = (warp_n >> 3) + np * 2 + (lane >> 4);
                uint32_t addr = bbase + 2u * (kr * 128 + ((c ^ (kr & 7)) * 8));
                ldsm_x4_t(addr, bf[np * 2][0], bf[np * 2][1],
                          bf[np * 2 + 1][0], bf[np * 2 + 1][1]);
            }
#pragma unroll
            for (int mt = 0; mt < 4; mt++)
#pragma unroll
                for (int nt = 0; nt < 4; nt++)
                    mma16816(acc[mt][nt], af[mt], bf[nt]);
        }
    };

    LOAD(0);
    STS(0);
    __syncthreads();
    for (int kt = 0; kt < ksteps; kt++) {
        if (kt + 1 < ksteps) LOAD(kt + 1);
        COMPUTE(kt & 1);
        if (kt + 1 < ksteps) STS((kt + 1) & 1);
        __syncthreads();
    }

    // epilogue: c-frag mapping (row = lane>>2 (+8), col = 2*(lane&3) (+1))
#pragma unroll
    for (int mt = 0; mt < 4; mt++) {
        int r0 = bm + warp_m + mt * 16 + (lane >> 2);
#pragma unroll
        for (int nt = 0; nt < 4; nt++) {
            int cc = bn + warp_n + nt * 8 + (lane & 3) * 2;
            float v00 = acc[mt][nt][0], v01 = acc[mt][nt][1];
            float v10 = acc[mt][nt][2], v11 = acc[mt][nt][3];
            if (BIAS) {
                float b0 = __ldg(bias + cc), b1 = __ldg(bias + cc + 1);
                v00 += b0; v01 += b1; v10 += b0; v11 += b1;
            }
            if (RELU) {
                v00 = fmaxf(v00, 0.f); v01 = fmaxf(v01, 0.f);
                v10 = fmaxf(v10, 0.f); v11 = fmaxf(v11, 0.f);
            }
            float2 w0 = {v00, v01}, w1 = {v10, v11};
            *(float2*)(C + (size_t)r0 * ldc + cc) = w0;
            *(float2*)(C + (size_t)(r0 + 8) * ldc + cc) = w1;
        }
    }
}

// -------------------- cat[:,256:768] = target_feats ------------------------
__global__ void fill_cat_kernel(const float* __restrict__ tf, float* __restrict__ cat) {
    int i = blockIdx.x * blockDim.x + threadIdx.x;  // float4 index, 8192*128 total
    int row = i >> 7;
    int c   = i & 127;
    float4 v = __ldg((const float4*)tf + i);
    ((float4*)(cat + (size_t)row * HDIM + NHID))[c] = v;
}

// -------------------- row log_softmax over 512 cols -------------------------
__global__ void __launch_bounds__(256) logsoftmax512(const float* __restrict__ X,
                                                     float* __restrict__ O) {
    __shared__ float sred[8];
    int row = blockIdx.x;
    int t = threadIdx.x;
    const float* x = X + (size_t)row * 512;
    float v0 = x[t];
    float v1 = x[t + 256];

    float m = fmaxf(v0, v1);
#pragma unroll
    for (int o = 16; o > 0; o >>= 1) m = fmaxf(m, __shfl_xor_sync(0xffffffffu, m, o));
    if ((t & 31) == 0) sred[t >> 5] = m;
    __syncthreads();
    float bm = sred[0];
#pragma unroll
    for (int i = 1; i < 8; i++) bm = fmaxf(bm, sred[i]);
    __syncthreads();

    float s = expf(v0 - bm) + expf(v1 - bm);
#pragma unroll
    for (int o = 16; o > 0; o >>= 1) s += __shfl_xor_sync(0xffffffffu, s, o);
    if ((t & 31) == 0) sred[t >> 5] = s;
    __syncthreads();
    float bs = 0.f;
#pragma unroll
    for (int i = 0; i < 8; i++) bs += sred[i];

    float lse = bm + logf(bs);
    O[(size_t)row * 512 + t] = v0 - lse;
    O[(size_t)row * 512 + t + 256] = v1 - lse;
}

// -------------------- launch ------------------------------------------------
extern "C" void kernel_launch(void* const* d_in, const int* in_sizes, int n_in,
                              void* d_out, int out_size) {
    const float* x    = (const float*)d_in[0];
    const float* tf   = (const float*)d_in[1];
    const float* adj0 = (const float*)d_in[2];
    const float* adj1 = (const float*)d_in[3];
    const float* gc1w = (const float*)d_in[4];
    const float* gc1b = (const float*)d_in[5];
    const float* gc2w = (const float*)d_in[6];
    const float* gc2b = (const float*)d_in[7];
    const float* l1w  = (const float*)d_in[8];
    const float* l1b  = (const float*)d_in[9];
    const float* l2w  = (const float*)d_in[10];
    const float* l2b  = (const float*)d_in[11];
    const float* l3w  = (const float*)d_in[12];
    const float* l3b  = (const float*)d_in[13];
    float* out = (float*)d_out;

    void* sp = nullptr;
    cudaGetSymbolAddress(&sp, g_scratch);
    float* t1  = (float*)sp;
    float* h1  = t1 + NROWS * NHID;
    float* t2  = h1 + NROWS * NHID;
    float* cat = t2 + NROWS * NHID;
    float* o4  = cat + NROWS * HDIM;
    float* o5  = o4 + NROWS * HDIM;
    float* o6  = o5 + NROWS * HDIM;

    dim3 thr(256);
    // t1 = x @ gc1_w
    gemm_kernel<false, false><<<dim3(NHID / 128, NROWS / 128), thr>>>(
        x, gc1w, nullptr, t1, NROWS, NHID, NFEAT, NHID);
    // h1 = relu(adj0 @ t1 + gc1_b)
    gemm_kernel<true, true><<<dim3(NHID / 128, NROWS / 128), thr>>>(
        adj0, t1, gc1b, h1, NROWS, NHID, NROWS, NHID);
    // t2 = h1 @ gc2_w
    gemm_kernel<false, false><<<dim3(NHID / 128, NROWS / 128), thr>>>(
        h1, gc2w, nullptr, t2, NROWS, NHID, NHID, NHID);
    // cat[:, :256] = adj1 @ t2 + gc2_b   (ldc = 768)
    gemm_kernel<true, false><<<dim3(NHID / 128, NROWS / 128), thr>>>(
        adj1, t2, gc2b, cat, NROWS, NHID, NROWS, HDIM);
    // cat[:, 256:] = target_feats
    fill_cat_kernel<<<(NROWS * NFEAT / 4) / 256, 256>>>(tf, cat);
    // o4 = relu(cat @ lin1_w + lin1_b)
    gemm_kernel<true, true><<<dim3(HDIM / 128, NROWS / 128), thr>>>(
        cat, l1w, l1b, o4, NROWS, HDIM, HDIM, HDIM);
    // o5 = relu(o4 @ lin2_w + lin2_b)
    gemm_kernel<true, true><<<dim3(HDIM / 128, NROWS / 128), thr>>>(
        o4, l2w, l2b, o5, NROWS, HDIM, HDIM, HDIM);
    // o6 = o5 @ lin3_w + lin3_b
    gemm_kernel<true, false><<<dim3(NFEAT / 128, NROWS / 128), thr>>>(
        o5, l3w, l3b, o6, NROWS, NFEAT, HDIM, NFEAT);
    // out = log_softmax(o6, axis=1)
    logsoftmax512<<<NROWS, 256>>>(o6, out);

    (void)in_sizes; (void)n_in; (void)out_size;
}

// round 15
// speedup vs baseline: 1.5551x; 1.5551x over previous
#include <cuda_runtime.h>
#include <cuda_bf16.h>
#include <cstdint>

#define NROWS 8192
#define NFEAT 512
#define NHID  256
#define HDIM  768

// -------------------- scratch (device globals) ------------------------------
__device__ __align__(16) __nv_bfloat16 g_w1[NFEAT * NHID];
__device__ __align__(16) __nv_bfloat16 g_w2[NHID * NHID];
__device__ __align__(16) __nv_bfloat16 g_w3[HDIM * HDIM];
__device__ __align__(16) __nv_bfloat16 g_w4[HDIM * HDIM];
__device__ __align__(16) __nv_bfloat16 g_w5[HDIM * NFEAT];
__device__ __align__(16) __nv_bfloat16 g_t1[NROWS * NHID];
__device__ __align__(16) __nv_bfloat16 g_h1[NROWS * NHID];
__device__ __align__(16) __nv_bfloat16 g_t2[NROWS * NHID];
__device__ __align__(16) __nv_bfloat16 g_cat[NROWS * HDIM];
__device__ __align__(16) __nv_bfloat16 g_o4[NROWS * HDIM];
__device__ __align__(16) __nv_bfloat16 g_o5[NROWS * HDIM];
__device__ __align__(16) float        g_o6[NROWS * NFEAT];

// -------------------- small helpers -----------------------------------------
__device__ __forceinline__ void stchunk(void* dst, float4 x, float4 y) {
    __nv_bfloat162 p0(__float2bfloat16(x.x), __float2bfloat16(x.y));
    __nv_bfloat162 p1(__float2bfloat16(x.z), __float2bfloat16(x.w));
    __nv_bfloat162 p2(__float2bfloat16(y.x), __float2bfloat16(y.y));
    __nv_bfloat162 p3(__float2bfloat16(y.z), __float2bfloat16(y.w));
    uint4 u;
    u.x = *(uint32_t*)&p0; u.y = *(uint32_t*)&p1;
    u.z = *(uint32_t*)&p2; u.w = *(uint32_t*)&p3;
    *(uint4*)dst = u;
}
__device__ __forceinline__ void cp16(uint32_t s, const void* g) {
    asm volatile("cp.async.cg.shared.global [%0], [%1], 16;\n" :: "r"(s), "l"(g));
}
__device__ __forceinline__ void cp_commit() {
    asm volatile("cp.async.commit_group;\n" ::);
}
template <int N>
__device__ __forceinline__ void cp_wait() {
    asm volatile("cp.async.wait_group %0;\n" :: "n"(N));
}
__device__ __forceinline__ void ldsm_x4(uint32_t addr, uint32_t& r0, uint32_t& r1,
                                        uint32_t& r2, uint32_t& r3) {
    asm volatile("ldmatrix.sync.aligned.m8n8.x4.shared.b16 {%0,%1,%2,%3}, [%4];"
                 : "=r"(r0), "=r"(r1), "=r"(r2), "=r"(r3) : "r"(addr));
}
__device__ __forceinline__ void ldsm_x4_t(uint32_t addr, uint32_t& r0, uint32_t& r1,
                                          uint32_t& r2, uint32_t& r3) {
    asm volatile("ldmatrix.sync.aligned.m8n8.x4.trans.shared.b16 {%0,%1,%2,%3}, [%4];"
                 : "=r"(r0), "=r"(r1), "=r"(r2), "=r"(r3) : "r"(addr));
}
__device__ __forceinline__ void mma16816(float* d, const uint32_t* a, const uint32_t* b) {
    asm volatile(
        "mma.sync.aligned.m16n8k16.row.col.f32.bf16.bf16.f32 "
        "{%0,%1,%2,%3},{%4,%5,%6,%7},{%8,%9},{%0,%1,%2,%3};"
        : "+f"(d[0]), "+f"(d[1]), "+f"(d[2]), "+f"(d[3])
        : "r"(a[0]), "r"(a[1]), "r"(a[2]), "r"(a[3]), "r"(b[0]), "r"(b[1]));
}
__device__ __forceinline__ void st2(float* p, float a, float b) {
    *(float2*)p = make_float2(a, b);
}
__device__ __forceinline__ void st2(__nv_bfloat16* p, float a, float b) {
    __nv_bfloat162 v(__float2bfloat16(a), __float2bfloat16(b));
    *(__nv_bfloat162*)p = v;
}

// -------------------- GEMM --------------------------------------------------
// C[M,N] = act(A[M,K] @ B[K,N] + bias).  B is bf16 row-major (cp.async 4-stage).
// A is fp32 (AF32: LDG+cvt+STS, issued 4 ksteps ahead) or bf16 (cp.async).
// Block tile 64x128x64, 256 threads (8 warps 2x4, warp tile 32x32), 2 CTAs/SM.
// Requires M%64==0, N%128==0, K%64==0, K>=256, lda==K, ldb==N.
#define SMEM_BYTES (96 * 1024)

template <bool AF32, typename OutT, bool BIAS, bool RELU>
__global__ void __launch_bounds__(256, 2)
gemm(const void* __restrict__ Av, const __nv_bfloat16* __restrict__ B,
     const float* __restrict__ bias, OutT* __restrict__ C,
     int M, int N, int K, int ldc) {
    extern __shared__ char sm[];
    // layout: sA 4 stages x 8KB at [0,32KB); sB 4 stages x 16KB at [32KB,96KB)
    const int tid  = threadIdx.x;
    const int lane = tid & 31;
    const int wid  = tid >> 5;
    const int bm   = blockIdx.y * 64;
    const int bn   = blockIdx.x * 128;
    const int warp_m = (wid >> 2) * 32;   // 0 / 32
    const int warp_n = (wid & 3) * 32;    // 0..96

    const uint32_t sAb = (uint32_t)__cvta_generic_to_shared(sm);
    const uint32_t sBb = sAb + 32768;

    // ---- B loader: 64x128 bf16 = 1024 chunks; thread -> rows (tid>>4)+16j, chunk tid&15
    const int br = tid >> 4, bc = tid & 15;
    const __nv_bfloat16* Bg = B + (size_t)br * N + bn + bc * 8;
    const uint32_t sboff = (uint32_t)(br * 16 + (bc ^ (br & 7))) * 16;  // +4096 per 16 rows

    // ---- A bf16 loader: 64x64 = 512 chunks; rows (tid>>3)+32j, chunk tid&7
    const int ar = tid >> 3, ac = tid & 7;
    const __nv_bfloat16* Agb = (const __nv_bfloat16*)Av + (size_t)(bm + ar) * K + ac * 8;
    const uint32_t saoff_b = (uint32_t)(ar * 8 + (ac ^ (ar & 7))) * 16;  // +4096 for +32 rows

    // ---- A fp32 loader: row tid>>2, fp32-chunk cols {8*acf.., 8*(acf+4)..}
    const int arf = tid >> 2, acf = tid & 3;
    const float* Agf = (const float*)Av + (size_t)(bm + arf) * K + acf * 8;
    const uint32_t saoff_f0 = (uint32_t)(arf * 8 + (acf ^ (arf & 7))) * 16;
    const uint32_t saoff_f1 = (uint32_t)(arf * 8 + ((acf + 4) ^ (arf & 7))) * 16;

    float acc[2][4][4];
#pragma unroll
    for (int i = 0; i < 2; i++)
#pragma unroll
        for (int j = 0; j < 4; j++)
#pragma unroll
            for (int r = 0; r < 4; r++) acc[i][j][r] = 0.0f;

    const int ks = K >> 6;

    auto CPB = [&](int st, int kt) {
        uint32_t d = sBb + st * 16384 + sboff;
        const __nv_bfloat16* g = Bg + (size_t)kt * 64 * N;
#pragma unroll
        for (int j = 0; j < 4; j++) cp16(d + j * 4096, g + (size_t)j * 16 * N);
    };
    auto CPA = [&](int st, int kt) {
        uint32_t d = sAb + st * 8192 + saoff_b;
        const __nv_bfloat16* g = Agb + kt * 64;
        cp16(d, g);
        cp16(d + 4096, g + (size_t)32 * K);
    };
    auto LDGA = [&](float4 (&r)[4], int kt) {
        const float* p = Agf + kt * 64;
        r[0] = __ldg((const float4*)p);
        r[1] = __ldg((const float4*)(p + 4));
        r[2] = __ldg((const float4*)(p + 32));
        r[3] = __ldg((const float4*)(p + 36));
    };
    auto STSA = [&](int st, float4 (&r)[4]) {
        char* d = sm + st * 8192;
        stchunk(d + saoff_f0, r[0], r[1]);
        stchunk(d + saoff_f1, r[2], r[3]);
    };
    auto COMPUTE = [&](int st) {
        const uint32_t ab = sAb + st * 8192;
        const uint32_t bb = sBb + st * 16384;
#pragma unroll
        for (int kk = 0; kk < 4; kk++) {
            uint32_t af[2][4];
#pragma unroll
            for (int mt = 0; mt < 2; mt++) {
                int r = warp_m + mt * 16 + (lane & 7) + ((lane >> 3) & 1) * 8;
                int c = kk * 2 + (lane >> 4);
                uint32_t addr = ab + (uint32_t)(r * 8 + (c ^ (r & 7))) * 16;
                ldsm_x4(addr, af[mt][0], af[mt][1], af[mt][2], af[mt][3]);
            }
            uint32_t bf[4][2];
#pragma unroll
            for (int np = 0; np < 2; np++) {
                int kr = kk * 16 + (lane & 7) + ((lane >> 3) & 1) * 8;
                int c  = (warp_n >> 3) + np * 2 + (lane >> 4);
                uint32_t addr = bb + (uint32_t)(kr * 16 + (c ^ (kr & 7))) * 16;
                ldsm_x4_t(addr, bf[np * 2][0], bf[np * 2][1],
                          bf[np * 2 + 1][0], bf[np * 2 + 1][1]);
            }
#pragma unroll
            for (int mt = 0; mt < 2; mt++)
#pragma unroll
                for (int nt = 0; nt < 4; nt++)
                    mma16816(acc[mt][nt], af[mt], bf[nt]);
        }
    };

    float4 rs0[4], rs1[4];

    // ---- prologue (ks >= 4 always holds here) ----
    if constexpr (AF32) { LDGA(rs0, 0); LDGA(rs1, 1); }
#pragma unroll
    for (int s = 0; s < 3; s++) {
        if constexpr (!AF32) CPA(s, s);
        CPB(s, s);
        cp_commit();
    }
    if constexpr (AF32) {
        STSA(0, rs0);
        STSA(1, rs1);
        LDGA(rs0, 2);
        LDGA(rs1, 3);
    }

    auto ITER = [&](int kt, float4 (&rsv)[4]) {
        cp_wait<2>();
        __syncthreads();
        if constexpr (AF32) {
            if (kt + 2 < ks) STSA((kt + 2) & 3, rsv);
            if (kt + 4 < ks) LDGA(rsv, kt + 4);
        } else {
            if (kt + 3 < ks) CPA((kt + 3) & 3, kt + 3);
        }
        if (kt + 3 < ks) CPB((kt + 3) & 3, kt + 3);
        cp_commit();
        COMPUTE(kt & 3);
    };

    for (int kt = 0; kt < ks; kt += 2) {  // ks is even for all our shapes
        ITER(kt, rs0);
        ITER(kt + 1, rs1);
    }

    // ---- epilogue ----
#pragma unroll
    for (int mt = 0; mt < 2; mt++) {
        int r0 = bm + warp_m + mt * 16 + (lane >> 2);
#pragma unroll
        for (int nt = 0; nt < 4; nt++) {
            int cc = bn + warp_n + nt * 8 + (lane & 3) * 2;
            float v00 = acc[mt][nt][0], v01 = acc[mt][nt][1];
            float v10 = acc[mt][nt][2], v11 = acc[mt][nt][3];
            if (BIAS) {
                float b0 = __ldg(bias + cc), b1 = __ldg(bias + cc + 1);
                v00 += b0; v01 += b1; v10 += b0; v11 += b1;
            }
            if (RELU) {
                v00 = fmaxf(v00, 0.f); v01 = fmaxf(v01, 0.f);
                v10 = fmaxf(v10, 0.f); v11 = fmaxf(v11, 0.f);
            }
            st2(C + (size_t)r0 * ldc + cc, v00, v01);
            st2(C + (size_t)(r0 + 8) * ldc + cc, v10, v11);
        }
    }
    (void)M;
}

// -------------------- converters --------------------------------------------
__global__ void cvt_kernel(const float* __restrict__ in, __nv_bfloat16* __restrict__ out,
                           int n4) {
    int i = blockIdx.x * blockDim.x + threadIdx.x;
    if (i >= n4) return;
    float4 v = __ldg((const float4*)in + i);
    __nv_bfloat162 a(__float2bfloat16(v.x), __float2bfloat16(v.y));
    __nv_bfloat162 b(__float2bfloat16(v.z), __float2bfloat16(v.w));
    uint2 u; u.x = *(uint32_t*)&a; u.y = *(uint32_t*)&b;
    *((uint2*)out + i) = u;
}

__global__ void tf_cat_kernel(const float* __restrict__ tf, __nv_bfloat16* __restrict__ cat) {
    int i = blockIdx.x * blockDim.x + threadIdx.x;  // NROWS*NFEAT/4
    int row = i >> 7;
    int c   = i & 127;
    float4 v = __ldg((const float4*)tf + i);
    __nv_bfloat162 a(__float2bfloat16(v.x), __float2bfloat16(v.y));
    __nv_bfloat162 b(__float2bfloat16(v.z), __float2bfloat16(v.w));
    uint2 u; u.x = *(uint32_t*)&a; u.y = *(uint32_t*)&b;
    *(uint2*)(cat + (size_t)row * HDIM + NHID + c * 4) = u;
}

// -------------------- row log_softmax over 512 cols --------------------------
__global__ void __launch_bounds__(256) logsoftmax512(const float* __restrict__ X,
                                                     float* __restrict__ O) {
    __shared__ float sred[8];
    int row = blockIdx.x;
    int t = threadIdx.x;
    const float* x = X + (size_t)row * 512;
    float v0 = x[t];
    float v1 = x[t + 256];

    float m = fmaxf(v0, v1);
#pragma unroll
    for (int o = 16; o > 0; o >>= 1) m = fmaxf(m, __shfl_xor_sync(0xffffffffu, m, o));
    if ((t & 31) == 0) sred[t >> 5] = m;
    __syncthreads();
    float bm = sred[0];
#pragma unroll
    for (int i = 1; i < 8; i++) bm = fmaxf(bm, sred[i]);
    __syncthreads();

    float s = expf(v0 - bm) + expf(v1 - bm);
#pragma unroll
    for (int o = 16; o > 0; o >>= 1) s += __shfl_xor_sync(0xffffffffu, s, o);
    if ((t & 31) == 0) sred[t >> 5] = s;
    __syncthreads();
    float bs = 0.f;
#pragma unroll
    for (int i = 0; i < 8; i++) bs += sred[i];

    float lse = bm + logf(bs);
    O[(size_t)row * 512 + t] = v0 - lse;
    O[(size_t)row * 512 + t + 256] = v1 - lse;
}

// -------------------- host side ----------------------------------------------
template <bool AF32, typename OutT, bool BIAS, bool RELU>
static void launch_gemm(const void* A, const __nv_bfloat16* B, const float* bias,
                        OutT* C, int M, int N, int K, int ldc) {
    cudaFuncSetAttribute(gemm<AF32, OutT, BIAS, RELU>,
                         cudaFuncAttributeMaxDynamicSharedMemorySize, SMEM_BYTES);
    gemm<AF32, OutT, BIAS, RELU><<<dim3(N / 128, M / 64), 256, SMEM_BYTES>>>(
        A, B, bias, C, M, N, K, ldc);
}

static void cvt(const float* in, __nv_bfloat16* out, int n) {
    int n4 = n / 4;
    cvt_kernel<<<(n4 + 255) / 256, 256>>>(in, out, n4);
}

extern "C" void kernel_launch(void* const* d_in, const int* in_sizes, int n_in,
                              void* d_out, int out_size) {
    const float* x    = (const float*)d_in[0];
    const float* tf   = (const float*)d_in[1];
    const float* adj0 = (const float*)d_in[2];
    const float* adj1 = (const float*)d_in[3];
    const float* gc1w = (const float*)d_in[4];
    const float* gc1b = (const float*)d_in[5];
    const float* gc2w = (const float*)d_in[6];
    const float* gc2b = (const float*)d_in[7];
    const float* l1w  = (const float*)d_in[8];
    const float* l1b  = (const float*)d_in[9];
    const float* l2w  = (const float*)d_in[10];
    const float* l2b  = (const float*)d_in[11];
    const float* l3w  = (const float*)d_in[12];
    const float* l3b  = (const float*)d_in[13];
    float* out = (float*)d_out;

    void *w1, *w2, *w3, *w4, *w5, *t1, *h1, *t2, *cat, *o4, *o5, *o6;
    cudaGetSymbolAddress(&w1, g_w1);  cudaGetSymbolAddress(&w2, g_w2);
    cudaGetSymbolAddress(&w3, g_w3);  cudaGetSymbolAddress(&w4, g_w4);
    cudaGetSymbolAddress(&w5, g_w5);  cudaGetSymbolAddress(&t1, g_t1);
    cudaGetSymbolAddress(&h1, g_h1);  cudaGetSymbolAddress(&t2, g_t2);
    cudaGetSymbolAddress(&cat, g_cat); cudaGetSymbolAddress(&o4, g_o4);
    cudaGetSymbolAddress(&o5, g_o5);  cudaGetSymbolAddress(&o6, g_o6);

    typedef __nv_bfloat16 bf;

    // weight conversions (tiny)
    cvt(gc1w, (bf*)w1, NFEAT * NHID);
    cvt(gc2w, (bf*)w2, NHID * NHID);
    cvt(l1w,  (bf*)w3, HDIM * HDIM);
    cvt(l2w,  (bf*)w4, HDIM * HDIM);
    cvt(l3w,  (bf*)w5, HDIM * NFEAT);
    // cat right half = target_feats (bf16)
    tf_cat_kernel<<<(NROWS * NFEAT / 4) / 256, 256>>>(tf, (bf*)cat);

    // t1 = x @ gc1_w                              (fp32 A path)
    launch_gemm<true, bf, false, false>(x, (const bf*)w1, nullptr, (bf*)t1,
                                        NROWS, NHID, NFEAT, NHID);
    // h1 = relu(adj0 @ t1 + gc1_b)                (fp32 A path)
    launch_gemm<true, bf, true, true>(adj0, (const bf*)t1, gc1b, (bf*)h1,
                                      NROWS, NHID, NROWS, NHID);
    // t2 = h1 @ gc2_w                             (bf16 A path)
    launch_gemm<false, bf, false, false>(h1, (const bf*)w2, nullptr, (bf*)t2,
                                         NROWS, NHID, NHID, NHID);
    // cat[:, :256] = adj1 @ t2 + gc2_b            (fp32 A path, ldc = 768)
    launch_gemm<true, bf, true, false>(adj1, (const bf*)t2, gc2b, (bf*)cat,
                                       NROWS, NHID, NROWS, HDIM);
    // o4 = relu(cat @ lin1_w + lin1_b)
    launch_gemm<false, bf, true, true>(cat, (const bf*)w3, l1b, (bf*)o4,
                                       NROWS, HDIM, HDIM, HDIM);
    // o5 = relu(o4 @ lin2_w + lin2_b)
    launch_gemm<false, bf, true, true>(o4, (const bf*)w4, l2b, (bf*)o5,
                                       NROWS, HDIM, HDIM, HDIM);
    // o6 = o5 @ lin3_w + lin3_b                   (fp32 output)
    launch_gemm<false, float, true, false>(o5, (const bf*)w5, l3b, (float*)o6,
                                           NROWS, NFEAT, HDIM, NFEAT);
    // out = log_softmax(o6)
    logsoftmax512<<<NROWS, 256>>>((const float*)o6, out);

    (void)in_sizes; (void)n_in; (void)out_size;
}

// round 16
// speedup vs baseline: 1.5606x; 1.0036x over previous
#include <cuda_runtime.h>
#include <cuda_bf16.h>
#include <cstdint>

#define NROWS 8192
#define NFEAT 512
#define NHID  256
#define HDIM  768

// -------------------- scratch (device globals) ------------------------------
__device__ __align__(16) __nv_bfloat16 g_w1[NFEAT * NHID];
__device__ __align__(16) __nv_bfloat16 g_w2[NHID * NHID];
__device__ __align__(16) __nv_bfloat16 g_w3[HDIM * HDIM];
__device__ __align__(16) __nv_bfloat16 g_w4[HDIM * HDIM];
__device__ __align__(16) __nv_bfloat16 g_w5[HDIM * NFEAT];
__device__ __align__(16) __nv_bfloat16 g_t1[NROWS * NHID];
__device__ __align__(16) __nv_bfloat16 g_h1[NROWS * NHID];
__device__ __align__(16) __nv_bfloat16 g_t2[NROWS * NHID];
__device__ __align__(16) __nv_bfloat16 g_cat[NROWS * HDIM];
__device__ __align__(16) __nv_bfloat16 g_o4[NROWS * HDIM];
__device__ __align__(16) __nv_bfloat16 g_o5[NROWS * HDIM];
__device__ __align__(16) float        g_o6[NROWS * NFEAT];

// -------------------- small helpers -----------------------------------------
__device__ __forceinline__ void stchunk(void* dst, float4 x, float4 y) {
    __nv_bfloat162 p0(__float2bfloat16(x.x), __float2bfloat16(x.y));
    __nv_bfloat162 p1(__float2bfloat16(x.z), __float2bfloat16(x.w));
    __nv_bfloat162 p2(__float2bfloat16(y.x), __float2bfloat16(y.y));
    __nv_bfloat162 p3(__float2bfloat16(y.z), __float2bfloat16(y.w));
    uint4 u;
    u.x = *(uint32_t*)&p0; u.y = *(uint32_t*)&p1;
    u.z = *(uint32_t*)&p2; u.w = *(uint32_t*)&p3;
    *(uint4*)dst = u;
}
__device__ __forceinline__ void cp16(uint32_t s, const void* g) {
    asm volatile("cp.async.cg.shared.global [%0], [%1], 16;\n" :: "r"(s), "l"(g));
}
__device__ __forceinline__ void cp_commit() {
    asm volatile("cp.async.commit_group;\n" ::);
}
template <int N>
__device__ __forceinline__ void cp_wait() {
    asm volatile("cp.async.wait_group %0;\n" :: "n"(N));
}
__device__ __forceinline__ void ldsm_x4(uint32_t addr, uint32_t& r0, uint32_t& r1,
                                        uint32_t& r2, uint32_t& r3) {
    asm volatile("ldmatrix.sync.aligned.m8n8.x4.shared.b16 {%0,%1,%2,%3}, [%4];"
                 : "=r"(r0), "=r"(r1), "=r"(r2), "=r"(r3) : "r"(addr));
}
__device__ __forceinline__ void ldsm_x4_t(uint32_t addr, uint32_t& r0, uint32_t& r1,
                                          uint32_t& r2, uint32_t& r3) {
    asm volatile("ldmatrix.sync.aligned.m8n8.x4.trans.shared.b16 {%0,%1,%2,%3}, [%4];"
                 : "=r"(r0), "=r"(r1), "=r"(r2), "=r"(r3) : "r"(addr));
}
__device__ __forceinline__ void mma16816(float* d, const uint32_t* a, const uint32_t* b) {
    asm volatile(
        "mma.sync.aligned.m16n8k16.row.col.f32.bf16.bf16.f32 "
        "{%0,%1,%2,%3},{%4,%5,%6,%7},{%8,%9},{%0,%1,%2,%3};"
        : "+f"(d[0]), "+f"(d[1]), "+f"(d[2]), "+f"(d[3])
        : "r"(a[0]), "r"(a[1]), "r"(a[2]), "r"(a[3]), "r"(b[0]), "r"(b[1]));
}
__device__ __forceinline__ void st2(float* p, float a, float b) {
    *(float2*)p = make_float2(a, b);
}
__device__ __forceinline__ void st2(__nv_bfloat16* p, float a, float b) {
    __nv_bfloat162 v(__float2bfloat16(a), __float2bfloat16(b));
    *(__nv_bfloat162*)p = v;
}

// -------------------- GEMM --------------------------------------------------
// C[M,N] = act(A[M,K] @ B[K,N] + bias).  B is bf16 row-major (cp.async 4-stage).
// A is fp32 (AF32: LDG+cvt+STS, issued 4 ksteps ahead) or bf16 (cp.async).
// Block tile 64x128x64, 256 threads (8 warps 2x4, warp tile 32x32), 2 CTAs/SM.
// Requires M%64==0, N%128==0, K%64==0, K>=256, lda==K, ldb==N.
#define SMEM_BYTES (96 * 1024)

template <bool AF32, typename OutT, bool BIAS, bool RELU>
__global__ void __launch_bounds__(256, 2)
gemm(const void* __restrict__ Av, const __nv_bfloat16* __restrict__ B,
     const float* __restrict__ bias, OutT* __restrict__ C,
     int M, int N, int K, int ldc) {
    extern __shared__ char sm[];
    // layout: sA 4 stages x 8KB at [0,32KB); sB 4 stages x 16KB at [32KB,96KB)
    const int tid  = threadIdx.x;
    const int lane = tid & 31;
    const int wid  = tid >> 5;
    const int bm   = blockIdx.y * 64;
    const int bn   = blockIdx.x * 128;
    const int warp_m = (wid >> 2) * 32;   // 0 / 32
    const int warp_n = (wid & 3) * 32;    // 0..96

    const uint32_t sAb = (uint32_t)__cvta_generic_to_shared(sm);
    const uint32_t sBb = sAb + 32768;

    // ---- B loader: 64x128 bf16 = 1024 chunks; thread -> rows (tid>>4)+16j, chunk tid&15
    const int br = tid >> 4, bc = tid & 15;
    const __nv_bfloat16* Bg = B + (size_t)br * N + bn + bc * 8;
    const uint32_t sboff = (uint32_t)(br * 16 + (bc ^ (br & 7))) * 16;  // +4096 per 16 rows

    // ---- A bf16 loader: 64x64 = 512 chunks; rows (tid>>3)+32j, chunk tid&7
    const int ar = tid >> 3, ac = tid & 7;
    const __nv_bfloat16* Agb = (const __nv_bfloat16*)Av + (size_t)(bm + ar) * K + ac * 8;
    const uint32_t saoff_b = (uint32_t)(ar * 8 + (ac ^ (ar & 7))) * 16;  // +4096 for +32 rows

    // ---- A fp32 loader: row tid>>2, fp32-chunk cols {8*acf.., 8*(acf+4)..}
    const int arf = tid >> 2, acf = tid & 3;
    const float* Agf = (const float*)Av + (size_t)(bm + arf) * K + acf * 8;
    const uint32_t saoff_f0 = (uint32_t)(arf * 8 + (acf ^ (arf & 7))) * 16;
    const uint32_t saoff_f1 = (uint32_t)(arf * 8 + ((acf + 4) ^ (arf & 7))) * 16;

    float acc[2][4][4];
#pragma unroll
    for (int i = 0; i < 2; i++)
#pragma unroll
        for (int j = 0; j < 4; j++)
#pragma unroll
            for (int r = 0; r < 4; r++) acc[i][j][r] = 0.0f;

    const int ks = K >> 6;

    auto CPB = [&](int st, int kt) {
        uint32_t d = sBb + st * 16384 + sboff;
        const __nv_bfloat16* g = Bg + (size_t)kt * 64 * N;
#pragma unroll
        for (int j = 0; j < 4; j++) cp16(d + j * 4096, g + (size_t)j * 16 * N);
    };
    auto CPA = [&](int st, int kt) {
        uint32_t d = sAb + st * 8192 + saoff_b;
        const __nv_bfloat16* g = Agb + kt * 64;
        cp16(d, g);
        cp16(d + 4096, g + (size_t)32 * K);
    };
    auto LDGA = [&](float4 (&r)[4], int kt) {
        const float* p = Agf + kt * 64;
        r[0] = __ldg((const float4*)p);
        r[1] = __ldg((const float4*)(p + 4));
        r[2] = __ldg((const float4*)(p + 32));
        r[3] = __ldg((const float4*)(p + 36));
    };
    auto STSA = [&](int st, float4 (&r)[4]) {
        char* d = sm + st * 8192;
        stchunk(d + saoff_f0, r[0], r[1]);
        stchunk(d + saoff_f1, r[2], r[3]);
    };
    auto COMPUTE = [&](int st) {
        const uint32_t ab = sAb + st * 8192;
        const uint32_t bb = sBb + st * 16384;
#pragma unroll
        for (int kk = 0; kk < 4; kk++) {
            uint32_t af[2][4];
#pragma unroll
            for (int mt = 0; mt < 2; mt++) {
                int r = warp_m + mt * 16 + (lane & 7) + ((lane >> 3) & 1) * 8;
                int c = kk * 2 + (lane >> 4);
                uint32_t addr = ab + (uint32_t)(r * 8 + (c ^ (r & 7))) * 16;
                ldsm_x4(addr, af[mt][0], af[mt][1], af[mt][2], af[mt][3]);
            }
            uint32_t bf[4][2];
#pragma unroll
            for (int np = 0; np < 2; np++) {
                int kr = kk * 16 + (lane & 7) + ((lane >> 3) & 1) * 8;
                int c  = (warp_n >> 3) + np * 2 + (lane >> 4);
                uint32_t addr = bb + (uint32_t)(kr * 16 + (c ^ (kr & 7))) * 16;
                ldsm_x4_t(addr, bf[np * 2][0], bf[np * 2][1],
                          bf[np * 2 + 1][0], bf[np * 2 + 1][1]);
            }
#pragma unroll
            for (int mt = 0; mt < 2; mt++)
#pragma unroll
                for (int nt = 0; nt < 4; nt++)
                    mma16816(acc[mt][nt], af[mt], bf[nt]);
        }
    };

    float4 rs0[4], rs1[4];

    // ---- prologue (ks >= 4 always holds here) ----
    if constexpr (AF32) { LDGA(rs0, 0); LDGA(rs1, 1); }
#pragma unroll
    for (int s = 0; s < 3; s++) {
        if constexpr (!AF32) CPA(s, s);
        CPB(s, s);
        cp_commit();
    }
    if constexpr (AF32) {
        STSA(0, rs0);
        STSA(1, rs1);
        LDGA(rs0, 2);
        LDGA(rs1, 3);
    }

    auto ITER = [&](int kt, float4 (&rsv)[4]) {
        cp_wait<2>();
        __syncthreads();
        if constexpr (AF32) {
            if (kt + 2 < ks) STSA((kt + 2) & 3, rsv);
            if (kt + 4 < ks) LDGA(rsv, kt + 4);
        } else {
            if (kt + 3 < ks) CPA((kt + 3) & 3, kt + 3);
        }
        if (kt + 3 < ks) CPB((kt + 3) & 3, kt + 3);
        cp_commit();
        COMPUTE(kt & 3);
    };

    for (int kt = 0; kt < ks; kt += 2) {  // ks is even for all our shapes
        ITER(kt, rs0);
        ITER(kt + 1, rs1);
    }

    // ---- epilogue ----
#pragma unroll
    for (int mt = 0; mt < 2; mt++) {
        int r0 = bm + warp_m + mt * 16 + (lane >> 2);
#pragma unroll
        for (int nt = 0; nt < 4; nt++) {
            int cc = bn + warp_n + nt * 8 + (lane & 3) * 2;
            float v00 = acc[mt][nt][0], v01 = acc[mt][nt][1];
            float v10 = acc[mt][nt][2], v11 = acc[mt][nt][3];
            if (BIAS) {
                float b0 = __ldg(bias + cc), b1 = __ldg(bias + cc + 1);
                v00 += b0; v01 += b1; v10 += b0; v11 += b1;
            }
            if (RELU) {
                v00 = fmaxf(v00, 0.f); v01 = fmaxf(v01, 0.f);
                v10 = fmaxf(v10, 0.f); v11 = fmaxf(v11, 0.f);
            }
            st2(C + (size_t)r0 * ldc + cc, v00, v01);
            st2(C + (size_t)(r0 + 8) * ldc + cc, v10, v11);
        }
    }
    (void)M;
}

// -------------------- converters --------------------------------------------
__global__ void cvt_kernel(const float* __restrict__ in, __nv_bfloat16* __restrict__ out,
                           int n4) {
    int i = blockIdx.x * blockDim.x + threadIdx.x;
    if (i >= n4) return;
    float4 v = __ldg((const float4*)in + i);
    __nv_bfloat162 a(__float2bfloat16(v.x), __float2bfloat16(v.y));
    __nv_bfloat162 b(__float2bfloat16(v.z), __float2bfloat16(v.w));
    uint2 u; u.x = *(uint32_t*)&a; u.y = *(uint32_t*)&b;
    *((uint2*)out + i) = u;
}

__global__ void tf_cat_kernel(const float* __restrict__ tf, __nv_bfloat16* __restrict__ cat) {
    int i = blockIdx.x * blockDim.x + threadIdx.x;  // NROWS*NFEAT/4
    int row = i >> 7;
    int c   = i & 127;
    float4 v = __ldg((const float4*)tf + i);
    __nv_bfloat162 a(__float2bfloat16(v.x), __float2bfloat16(v.y));
    __nv_bfloat162 b(__float2bfloat16(v.z), __float2bfloat16(v.w));
    uint2 u; u.x = *(uint32_t*)&a; u.y = *(uint32_t*)&b;
    *(uint2*)(cat + (size_t)row * HDIM + NHID + c * 4) = u;
}

// -------------------- row log_softmax over 512 cols --------------------------
__global__ void __launch_bounds__(256) logsoftmax512(const float* __restrict__ X,
                                                     float* __restrict__ O) {
    __shared__ float sred[8];
    int row = blockIdx.x;
    int t = threadIdx.x;
    const float* x = X + (size_t)row * 512;
    float v0 = x[t];
    float v1 = x[t + 256];

    float m = fmaxf(v0, v1);
#pragma unroll
    for (int o = 16; o > 0; o >>= 1) m = fmaxf(m, __shfl_xor_sync(0xffffffffu, m, o));
    if ((t & 31) == 0) sred[t >> 5] = m;
    __syncthreads();
    float bm = sred[0];
#pragma unroll
    for (int i = 1; i < 8; i++) bm = fmaxf(bm, sred[i]);
    __syncthreads();

    float s = expf(v0 - bm) + expf(v1 - bm);
#pragma unroll
    for (int o = 16; o > 0; o >>= 1) s += __shfl_xor_sync(0xffffffffu, s, o);
    if ((t & 31) == 0) sred[t >> 5] = s;
    __syncthreads();
    float bs = 0.f;
#pragma unroll
    for (int i = 0; i < 8; i++) bs += sred[i];

    float lse = bm + logf(bs);
    O[(size_t)row * 512 + t] = v0 - lse;
    O[(size_t)row * 512 + t + 256] = v1 - lse;
}

// -------------------- host side ----------------------------------------------
template <bool AF32, typename OutT, bool BIAS, bool RELU>
static void launch_gemm(const void* A, const __nv_bfloat16* B, const float* bias,
                        OutT* C, int M, int N, int K, int ldc) {
    cudaFuncSetAttribute(gemm<AF32, OutT, BIAS, RELU>,
                         cudaFuncAttributeMaxDynamicSharedMemorySize, SMEM_BYTES);
    gemm<AF32, OutT, BIAS, RELU><<<dim3(N / 128, M / 64), 256, SMEM_BYTES>>>(
        A, B, bias, C, M, N, K, ldc);
}

static void cvt(const float* in, __nv_bfloat16* out, int n) {
    int n4 = n / 4;
    cvt_kernel<<<(n4 + 255) / 256, 256>>>(in, out, n4);
}

extern "C" void kernel_launch(void* const* d_in, const int* in_sizes, int n_in,
                              void* d_out, int out_size) {
    const float* x    = (const float*)d_in[0];
    const float* tf   = (const float*)d_in[1];
    const float* adj0 = (const float*)d_in[2];
    const float* adj1 = (const float*)d_in[3];
    const float* gc1w = (const float*)d_in[4];
    const float* gc1b = (const float*)d_in[5];
    const float* gc2w = (const float*)d_in[6];
    const float* gc2b = (const float*)d_in[7];
    const float* l1w  = (const float*)d_in[8];
    const float* l1b  = (const float*)d_in[9];
    const float* l2w  = (const float*)d_in[10];
    const float* l2b  = (const float*)d_in[11];
    const float* l3w  = (const float*)d_in[12];
    const float* l3b  = (const float*)d_in[13];
    float* out = (float*)d_out;

    void *w1, *w2, *w3, *w4, *w5, *t1, *h1, *t2, *cat, *o4, *o5, *o6;
    cudaGetSymbolAddress(&w1, g_w1);  cudaGetSymbolAddress(&w2, g_w2);
    cudaGetSymbolAddress(&w3, g_w3);  cudaGetSymbolAddress(&w4, g_w4);
    cudaGetSymbolAddress(&w5, g_w5);  cudaGetSymbolAddress(&t1, g_t1);
    cudaGetSymbolAddress(&h1, g_h1);  cudaGetSymbolAddress(&t2, g_t2);
    cudaGetSymbolAddress(&cat, g_cat); cudaGetSymbolAddress(&o4, g_o4);
    cudaGetSymbolAddress(&o5, g_o5);  cudaGetSymbolAddress(&o6, g_o6);

    typedef __nv_bfloat16 bf;

    // weight conversions (tiny)
    cvt(gc1w, (bf*)w1, NFEAT * NHID);
    cvt(gc2w, (bf*)w2, NHID * NHID);
    cvt(l1w,  (bf*)w3, HDIM * HDIM);
    cvt(l2w,  (bf*)w4, HDIM * HDIM);
    cvt(l3w,  (bf*)w5, HDIM * NFEAT);
    // cat right half = target_feats (bf16)
    tf_cat_kernel<<<(NROWS * NFEAT / 4) / 256, 256>>>(tf, (bf*)cat);

    // t1 = x @ gc1_w                              (fp32 A path)
    launch_gemm<true, bf, false, false>(x, (const bf*)w1, nullptr, (bf*)t1,
                                        NROWS, NHID, NFEAT, NHID);
    // h1 = relu(adj0 @ t1 + gc1_b)                (fp32 A path)
    launch_gemm<true, bf, true, true>(adj0, (const bf*)t1, gc1b, (bf*)h1,
                                      NROWS, NHID, NROWS, NHID);
    // t2 = h1 @ gc2_w                             (bf16 A path)
    launch_gemm<false, bf, false, false>(h1, (const bf*)w2, nullptr, (bf*)t2,
                                         NROWS, NHID, NHID, NHID);
    // cat[:, :256] = adj1 @ t2 + gc2_b            (fp32 A path, ldc = 768)
    launch_gemm<true, bf, true, false>(adj1, (const bf*)t2, gc2b, (bf*)cat,
                                       NROWS, NHID, NROWS, HDIM);
    // o4 = relu(cat @ lin1_w + lin1_b)
    launch_gemm<false, bf, true, true>(cat, (const bf*)w3, l1b, (bf*)o4,
                                       NROWS, HDIM, HDIM, HDIM);
    // o5 = relu(o4 @ lin2_w + lin2_b)
    launch_gemm<false, bf, true, true>(o4, (const bf*)w4, l2b, (bf*)o5,
                                       NROWS, HDIM, HDIM, HDIM);
    // o6 = o5 @ lin3_w + lin3_b                   (fp32 output)
    launch_gemm<false, float, true, false>(o5, (const bf*)w5, l3b, (float*)o6,
                                           NROWS, NFEAT, HDIM, NFEAT);
    // out = log_softmax(o6)
    logsoftmax512<<<NROWS, 256>>>((const float*)o6, out);

    (void)in_sizes; (void)n_in; (void)out_size;
}